// round 1
// baseline (speedup 1.0000x reference)
#include <cuda_runtime.h>
#include <math.h>

#define BN 4
#define CN 64
#define HN 128
#define WN 128
#define SN (HN*WN)      // 16384
#define NP (BN*SN)      // 65536

// Scratch (device globals; no allocations allowed)
__device__ float g_xT[NP*CN];   // x in NHWC
__device__ float g_y1[NP*CN];   // layer-1 output, NHWC
__device__ float g_rfh[NP];     // rf_h / 2
__device__ float g_rfw[NP];     // rf_w / 2

// ---------------------------------------------------------------------------
// Tiled transpose: src [b][rows][cols] -> dst [b][cols][rows]
// ---------------------------------------------------------------------------
__global__ void transpose_cs(float* __restrict__ dst, const float* __restrict__ src,
                             int rows, int cols)
{
    __shared__ float tile[32][33];
    int bz = blockIdx.z;
    const float* s = src + (size_t)bz * rows * cols;
    float*       d = dst + (size_t)bz * rows * cols;
    int c0 = blockIdx.x * 32, r0 = blockIdx.y * 32;
    #pragma unroll
    for (int i = 0; i < 4; i++) {
        int r = r0 + threadIdx.y + i * 8;
        int c = c0 + threadIdx.x;
        if (r < rows && c < cols)
            tile[threadIdx.y + i * 8][threadIdx.x] = s[(size_t)r * cols + c];
    }
    __syncthreads();
    #pragma unroll
    for (int i = 0; i < 4; i++) {
        int c = c0 + threadIdx.y + i * 8;
        int r = r0 + threadIdx.x;
        if (c < cols && r < rows)
            d[(size_t)c * rows + r] = tile[threadIdx.x][threadIdx.y + i * 8];
    }
}

// ---------------------------------------------------------------------------
// Offset conv: hw = sigmoid(conv3x3(x, w_off) + b_off); rf = lo + (hi-lo)*hw
// Stores rf/2 per pixel. Input NHWC, SAME zero padding.
// ---------------------------------------------------------------------------
__global__ __launch_bounds__(256)
void offset_conv(const float* __restrict__ xin,   // NHWC
                 const float* __restrict__ woff,  // [2][C][3][3]
                 const float* __restrict__ boff,  // [2]
                 const int* __restrict__ p_lo, const int* __restrict__ p_hi,
                 float* __restrict__ rfh, float* __restrict__ rfw)
{
    __shared__ float sw[9 * CN * 2];  // [k][c][j]
    for (int d = threadIdx.x; d < 9 * CN * 2; d += 256) {
        int k = d / (CN * 2);
        int c = (d / 2) % CN;
        int j = d & 1;
        sw[d] = woff[(j * CN + c) * 9 + k];
    }
    __syncthreads();

    int p  = blockIdx.x * 256 + threadIdx.x;
    int b  = p >> 14;
    int hw = p & (SN - 1);
    int h  = hw >> 7;
    int w  = hw & (WN - 1);

    float a0 = boff[0], a1 = boff[1];
    const float* xb = xin + (size_t)b * SN * CN;

    #pragma unroll 1
    for (int k = 0; k < 9; k++) {
        int yy = h + (k / 3) - 1;
        int xx = w + (k % 3) - 1;
        if (yy < 0 || yy >= HN || xx < 0 || xx >= WN) continue;  // zero pad
        const float4* v4 = (const float4*)(xb + (yy * WN + xx) * CN);
        const float2* w2 = (const float2*)(sw + k * CN * 2);
        #pragma unroll 4
        for (int cg = 0; cg < 16; cg++) {
            float4 v = v4[cg];
            float2 wa = w2[cg * 4 + 0];
            float2 wb = w2[cg * 4 + 1];
            float2 wc = w2[cg * 4 + 2];
            float2 wd = w2[cg * 4 + 3];
            a0 += v.x * wa.x + v.y * wb.x + v.z * wc.x + v.w * wd.x;
            a1 += v.x * wa.y + v.y * wb.y + v.z * wc.y + v.w * wd.y;
        }
    }

    float lo   = (float)(*p_lo);
    float span = (float)(*p_hi) - lo;
    float s0 = 1.f / (1.f + expf(-a0));
    float s1 = 1.f / (1.f + expf(-a1));
    rfh[p] = 0.5f * (lo + span * s0);
    rfw[p] = 0.5f * (lo + span * s1);
}

// ---------------------------------------------------------------------------
// Main ARConv kernel: per-pixel 9-tap bilinear gather + 64x576 contraction.
// mode 0: write NHWC with ReLU.  mode 1: add NCHW residual, write NCHW.
// ---------------------------------------------------------------------------
__global__ __launch_bounds__(256)
void arconv_main(const float* __restrict__ xin,        // NHWC input
                 const float* __restrict__ rfh, const float* __restrict__ rfw,
                 const float* __restrict__ Wk,          // [O][C][3][3]
                 const float* __restrict__ bias,        // [O]
                 const float* __restrict__ resid,       // NCHW x (mode 1) or null
                 float* __restrict__ outp,
                 int mode)
{
    extern __shared__ float sW[];  // [k][c][o] : 9*64*64 floats = 144 KB

    // Destination-indexed load: consecutive threads -> consecutive smem words.
    for (int d = threadIdx.x; d < 9 * CN * CN; d += 256) {
        int k = d >> 12;          // /4096
        int c = (d >> 6) & 63;
        int o = d & 63;
        sW[d] = Wk[(o * CN + c) * 9 + k];
    }
    __syncthreads();

    int p  = blockIdx.x * 256 + threadIdx.x;
    int b  = p >> 14;
    int hw = p & (SN - 1);
    int h  = hw >> 7;
    int w  = hw & (WN - 1);

    float acc[CN];
    #pragma unroll
    for (int i = 0; i < CN; i++) acc[i] = 0.f;

    float rh = rfh[p];
    float rw = rfw[p];
    const float* xb = xin + (size_t)b * SN * CN;

    #pragma unroll 1
    for (int k = 0; k < 9; k++) {
        float ys = (float)h + ((float)(k / 3) - 1.f) * rh;
        float xs = (float)w + ((float)(k % 3) - 1.f) * rw;
        float y0f = floorf(ys), x0f = floorf(xs);
        float ty = ys - y0f, tx = xs - x0f;
        int y0 = (int)y0f; y0 = min(max(y0, 0), HN - 1);
        int y1 = min(y0 + 1, HN - 1);
        int x0 = (int)x0f; x0 = min(max(x0, 0), WN - 1);
        int x1 = min(x0 + 1, WN - 1);
        float w11 = ty * tx;
        float w01 = tx - w11;
        float w10 = ty - w11;
        float w00 = 1.f - ty - tx + w11;

        const float4* p00 = (const float4*)(xb + (y0 * WN + x0) * CN);
        const float4* p01 = (const float4*)(xb + (y0 * WN + x1) * CN);
        const float4* p10 = (const float4*)(xb + (y1 * WN + x0) * CN);
        const float4* p11 = (const float4*)(xb + (y1 * WN + x1) * CN);
        const float* swk = sW + k * (CN * CN);

        #pragma unroll 1
        for (int cg = 0; cg < 16; cg++) {
            float4 a = p00[cg], bq = p01[cg], cq = p10[cg], dq = p11[cg];
            float sv[4];
            sv[0] = w00 * a.x + w01 * bq.x + w10 * cq.x + w11 * dq.x;
            sv[1] = w00 * a.y + w01 * bq.y + w10 * cq.y + w11 * dq.y;
            sv[2] = w00 * a.z + w01 * bq.z + w10 * cq.z + w11 * dq.z;
            sv[3] = w00 * a.w + w01 * bq.w + w10 * cq.w + w11 * dq.w;
            #pragma unroll
            for (int j = 0; j < 4; j++) {
                const float4* wr = (const float4*)(swk + (cg * 4 + j) * CN);
                float s = sv[j];
                #pragma unroll
                for (int og = 0; og < 16; og++) {
                    float4 wv = wr[og];
                    acc[4 * og + 0] += s * wv.x;
                    acc[4 * og + 1] += s * wv.y;
                    acc[4 * og + 2] += s * wv.z;
                    acc[4 * og + 3] += s * wv.w;
                }
            }
        }
    }

    if (mode == 0) {
        // ReLU, write NHWC (thread-contiguous float4 stores)
        float4* o4 = (float4*)(outp + (size_t)p * CN);
        #pragma unroll
        for (int og = 0; og < 16; og++) {
            float4 v;
            v.x = fmaxf(acc[4 * og + 0] + bias[4 * og + 0], 0.f);
            v.y = fmaxf(acc[4 * og + 1] + bias[4 * og + 1], 0.f);
            v.z = fmaxf(acc[4 * og + 2] + bias[4 * og + 2], 0.f);
            v.w = fmaxf(acc[4 * og + 3] + bias[4 * og + 3], 0.f);
            o4[og] = v;
        }
    } else {
        // Residual add + NCHW store. For each fixed o the warp's threads hit
        // consecutive hw -> fully coalesced loads/stores.
        #pragma unroll
        for (int o = 0; o < CN; o++) {
            size_t idx = ((size_t)(b * CN + o)) * SN + hw;
            outp[idx] = acc[o] + bias[o] + resid[idx];
        }
    }
}

// ---------------------------------------------------------------------------
extern "C" void kernel_launch(void* const* d_in, const int* in_sizes, int n_in,
                              void* d_out, int out_size)
{
    const float* x     = (const float*)d_in[0];
    const float* woff1 = (const float*)d_in[1];
    const float* boff1 = (const float*)d_in[2];
    const float* W1    = (const float*)d_in[3];
    const float* b1    = (const float*)d_in[4];
    const float* woff2 = (const float*)d_in[5];
    const float* boff2 = (const float*)d_in[6];
    const float* W2    = (const float*)d_in[7];
    const float* b2    = (const float*)d_in[8];
    const int*   lo    = (const int*)d_in[10];
    const int*   hi    = (const int*)d_in[11];
    float* out = (float*)d_out;

    float *xT, *y1, *rfh, *rfw;
    cudaGetSymbolAddress((void**)&xT,  g_xT);
    cudaGetSymbolAddress((void**)&y1,  g_y1);
    cudaGetSymbolAddress((void**)&rfh, g_rfh);
    cudaGetSymbolAddress((void**)&rfw, g_rfw);

    const int SMEM_W = 9 * CN * CN * (int)sizeof(float);  // 147456
    cudaFuncSetAttribute(arconv_main, cudaFuncAttributeMaxDynamicSharedMemorySize, SMEM_W);

    dim3 tb(32, 8);
    // x NCHW -> NHWC
    transpose_cs<<<dim3(SN / 32, CN / 32, BN), tb>>>(xT, x, CN, SN);

    // Layer 1
    offset_conv<<<NP / 256, 256>>>(xT, woff1, boff1, lo, hi, rfh, rfw);
    arconv_main<<<NP / 256, 256, SMEM_W>>>(xT, rfh, rfw, W1, b1, nullptr, y1, 0);

    // Layer 2 (+ residual, NCHW out)
    offset_conv<<<NP / 256, 256>>>(y1, woff2, boff2, lo, hi, rfh, rfw);
    arconv_main<<<NP / 256, 256, SMEM_W>>>(y1, rfh, rfw, W2, b2, x, out, 1);
}

// round 2
// speedup vs baseline: 2.3048x; 2.3048x over previous
#include <cuda_runtime.h>
#include <math.h>

#define BN 4
#define CN 64
#define HN 128
#define WN 128
#define SN (HN*WN)      // 16384
#define NP (BN*SN)      // 65536

// Scratch (device globals; no allocations allowed)
__device__ float g_y1[NP*CN];   // layer-1 output, NCHW
__device__ float g_rfh[NP];     // rf_h / 2
__device__ float g_rfw[NP];     // rf_w / 2

// ---------------------------------------------------------------------------
// Offset conv (NCHW): hw = sigmoid(conv3x3(x)+b); store rf/2 per pixel.
// One thread per pixel; per channel loads the 3x3 neighborhood (coalesced).
// ---------------------------------------------------------------------------
__global__ __launch_bounds__(256)
void offset_conv(const float* __restrict__ xin,   // NCHW
                 const float* __restrict__ woff,  // [2][C][3][3]
                 const float* __restrict__ boff,  // [2]
                 const int* __restrict__ p_lo, const int* __restrict__ p_hi,
                 float* __restrict__ rfh, float* __restrict__ rfw)
{
    __shared__ float sw[CN * 18];  // [c][k][j]
    for (int d = threadIdx.x; d < CN * 18; d += 256) {
        int c = d / 18;
        int k = (d % 18) >> 1;
        int j = d & 1;
        sw[d] = woff[(j * CN + c) * 9 + k];
    }
    __syncthreads();

    int p  = blockIdx.x * 256 + threadIdx.x;
    int b  = p >> 14;
    int hw = p & (SN - 1);
    int h  = hw >> 7;
    int w  = hw & (WN - 1);

    bool hm = h > 0, hp = h < HN - 1, wm = w > 0, wp = w < WN - 1;

    float a0 = boff[0], a1 = boff[1];
    const float* xb = xin + (size_t)b * CN * SN;

    #pragma unroll 2
    for (int c = 0; c < CN; c++) {
        const float* xc = xb + c * SN + hw;
        float v[9];
        v[4] = xc[0];
        v[1] = hm ? xc[-WN] : 0.f;
        v[7] = hp ? xc[ WN] : 0.f;
        v[3] = wm ? xc[-1] : 0.f;
        v[5] = wp ? xc[ 1] : 0.f;
        v[0] = (hm && wm) ? xc[-WN - 1] : 0.f;
        v[2] = (hm && wp) ? xc[-WN + 1] : 0.f;
        v[6] = (hp && wm) ? xc[ WN - 1] : 0.f;
        v[8] = (hp && wp) ? xc[ WN + 1] : 0.f;
        const float* wc = sw + c * 18;
        #pragma unroll
        for (int k = 0; k < 9; k++) {
            a0 += v[k] * wc[k * 2 + 0];
            a1 += v[k] * wc[k * 2 + 1];
        }
    }

    float lo   = (float)(*p_lo);
    float span = (float)(*p_hi) - lo;
    float s0 = 1.f / (1.f + __expf(-a0));
    float s1 = 1.f / (1.f + __expf(-a1));
    rfh[p] = 0.5f * (lo + span * s0);
    rfw[p] = 0.5f * (lo + span * s1);
}

// ---------------------------------------------------------------------------
// Main ARConv kernel (NCHW): per-pixel 9-tap bilinear gather (separable,
// 5x5 value grid = 25 coalesced scalar loads per channel) + 64x576
// contraction against smem weights.
// mode 0: ReLU, write NCHW.  mode 1: add NCHW residual, write NCHW.
// ---------------------------------------------------------------------------
__global__ __launch_bounds__(256)
void arconv_main(const float* __restrict__ xin,        // NCHW input
                 const float* __restrict__ rfh, const float* __restrict__ rfw,
                 const float* __restrict__ Wk,          // [O][C][3][3]
                 const float* __restrict__ bias,        // [O]
                 const float* __restrict__ resid,       // NCHW x (mode 1) or null
                 float* __restrict__ outp,
                 int mode)
{
    extern __shared__ float sW[];  // [k][c][o] : 9*64*64 floats = 144 KB

    for (int d = threadIdx.x; d < 9 * CN * CN; d += 256) {
        int k = d >> 12;
        int c = (d >> 6) & 63;
        int o = d & 63;
        sW[d] = Wk[(o * CN + c) * 9 + k];
    }
    __syncthreads();

    int p  = blockIdx.x * 256 + threadIdx.x;
    int b  = p >> 14;
    int hw = p & (SN - 1);
    int h  = hw >> 7;
    int w  = hw & (WN - 1);

    float rh = rfh[p];
    float rw = rfw[p];

    // x sampling columns: left (w - rw), center (w, exact), right (w + rw)
    float xsl = (float)w - rw;
    float xsr = (float)w + rw;
    float xl0f = floorf(xsl), xr0f = floorf(xsr);
    float txl = xsl - xl0f, txr = xsr - xr0f;
    int xl0 = min(max((int)xl0f, 0), WN - 1); int xl1 = min(xl0 + 1, WN - 1);
    int xr0 = min(max((int)xr0f, 0), WN - 1); int xr1 = min(xr0 + 1, WN - 1);

    // y sampling rows: top (h - rh), center (h, exact), bottom (h + rh)
    float ysa = (float)h - rh;
    float ysb = (float)h + rh;
    float ya0f = floorf(ysa), yb0f = floorf(ysb);
    float tya = ysa - ya0f, tyb = ysb - yb0f;
    int ya0 = min(max((int)ya0f, 0), HN - 1); int ya1 = min(ya0 + 1, HN - 1);
    int yb0 = min(max((int)yb0f, 0), HN - 1); int yb1 = min(yb0 + 1, HN - 1);

    int oa0 = ya0 * WN, oa1 = ya1 * WN;
    int oh  = h   * WN;
    int ob0 = yb0 * WN, ob1 = yb1 * WN;

    float acc[CN];
    #pragma unroll
    for (int i = 0; i < CN; i++) acc[i] = 0.f;

    const float* xb = xin + (size_t)b * CN * SN;

    #pragma unroll 1
    for (int c = 0; c < CN; c++) {
        const float* xc = xb + c * SN;
        // 5x5 value grid (rows: a0,a1,h,b0,b1 ; cols: l0,l1,w,r0,r1)
        float va0l0 = xc[oa0 + xl0], va0l1 = xc[oa0 + xl1], va0c = xc[oa0 + w],
              va0r0 = xc[oa0 + xr0], va0r1 = xc[oa0 + xr1];
        float va1l0 = xc[oa1 + xl0], va1l1 = xc[oa1 + xl1], va1c = xc[oa1 + w],
              va1r0 = xc[oa1 + xr0], va1r1 = xc[oa1 + xr1];
        float vhl0  = xc[oh  + xl0], vhl1  = xc[oh  + xl1], vhc  = xc[oh  + w],
              vhr0  = xc[oh  + xr0], vhr1  = xc[oh  + xr1];
        float vb0l0 = xc[ob0 + xl0], vb0l1 = xc[ob0 + xl1], vb0c = xc[ob0 + w],
              vb0r0 = xc[ob0 + xr0], vb0r1 = xc[ob0 + xr1];
        float vb1l0 = xc[ob1 + xl0], vb1l1 = xc[ob1 + xl1], vb1c = xc[ob1 + w],
              vb1r0 = xc[ob1 + xr0], vb1r1 = xc[ob1 + xr1];

        // x-lerps per row
        float la0 = fmaf(txl, va0l1 - va0l0, va0l0);
        float ra0 = fmaf(txr, va0r1 - va0r0, va0r0);
        float la1 = fmaf(txl, va1l1 - va1l0, va1l0);
        float ra1 = fmaf(txr, va1r1 - va1r0, va1r0);
        float lh  = fmaf(txl, vhl1  - vhl0,  vhl0);
        float rh2 = fmaf(txr, vhr1  - vhr0,  vhr0);
        float lb0 = fmaf(txl, vb0l1 - vb0l0, vb0l0);
        float rb0 = fmaf(txr, vb0r1 - vb0r0, vb0r0);
        float lb1 = fmaf(txl, vb1l1 - vb1l0, vb1l0);
        float rb1 = fmaf(txr, vb1r1 - vb1r0, vb1r0);

        // y-lerps -> 9 taps  (k = 3*rowgroup + col)
        float sv[9];
        sv[0] = fmaf(tya, la1  - la0,  la0);
        sv[1] = fmaf(tya, va1c - va0c, va0c);
        sv[2] = fmaf(tya, ra1  - ra0,  ra0);
        sv[3] = lh;
        sv[4] = vhc;
        sv[5] = rh2;
        sv[6] = fmaf(tyb, lb1  - lb0,  lb0);
        sv[7] = fmaf(tyb, vb1c - vb0c, vb0c);
        sv[8] = fmaf(tyb, rb1  - rb0,  rb0);

        // contraction: acc[o] += sv[k] * W[k][c][o]
        #pragma unroll
        for (int k = 0; k < 9; k++) {
            const float4* wr = (const float4*)(sW + (k * CN + c) * CN);
            float s = sv[k];
            #pragma unroll
            for (int og = 0; og < 16; og++) {
                float4 wv = wr[og];
                acc[4 * og + 0] += s * wv.x;
                acc[4 * og + 1] += s * wv.y;
                acc[4 * og + 2] += s * wv.z;
                acc[4 * og + 3] += s * wv.w;
            }
        }
    }

    if (mode == 0) {
        // ReLU, write NCHW (coalesced per-o stores)
        #pragma unroll
        for (int o = 0; o < CN; o++) {
            size_t idx = ((size_t)(b * CN + o)) * SN + hw;
            outp[idx] = fmaxf(acc[o] + bias[o], 0.f);
        }
    } else {
        // Residual add + NCHW store
        #pragma unroll
        for (int o = 0; o < CN; o++) {
            size_t idx = ((size_t)(b * CN + o)) * SN + hw;
            outp[idx] = acc[o] + bias[o] + resid[idx];
        }
    }
}

// ---------------------------------------------------------------------------
extern "C" void kernel_launch(void* const* d_in, const int* in_sizes, int n_in,
                              void* d_out, int out_size)
{
    const float* x     = (const float*)d_in[0];
    const float* woff1 = (const float*)d_in[1];
    const float* boff1 = (const float*)d_in[2];
    const float* W1    = (const float*)d_in[3];
    const float* b1    = (const float*)d_in[4];
    const float* woff2 = (const float*)d_in[5];
    const float* boff2 = (const float*)d_in[6];
    const float* W2    = (const float*)d_in[7];
    const float* b2    = (const float*)d_in[8];
    const int*   lo    = (const int*)d_in[10];
    const int*   hi    = (const int*)d_in[11];
    float* out = (float*)d_out;

    float *y1, *rfh, *rfw;
    cudaGetSymbolAddress((void**)&y1,  g_y1);
    cudaGetSymbolAddress((void**)&rfh, g_rfh);
    cudaGetSymbolAddress((void**)&rfw, g_rfw);

    const int SMEM_W = 9 * CN * CN * (int)sizeof(float);  // 147456
    cudaFuncSetAttribute(arconv_main, cudaFuncAttributeMaxDynamicSharedMemorySize, SMEM_W);

    // Layer 1 (x NCHW in, y1 NCHW out, ReLU)
    offset_conv<<<NP / 256, 256>>>(x, woff1, boff1, lo, hi, rfh, rfw);
    arconv_main<<<NP / 256, 256, SMEM_W>>>(x, rfh, rfw, W1, b1, nullptr, y1, 0);

    // Layer 2 (+ residual, NCHW out)
    offset_conv<<<NP / 256, 256>>>(y1, woff2, boff2, lo, hi, rfh, rfw);
    arconv_main<<<NP / 256, 256, SMEM_W>>>(y1, rfh, rfw, W2, b2, x, out, 1);
}

// round 4
// speedup vs baseline: 4.1336x; 1.7935x over previous
#include <cuda_runtime.h>
#include <cuda_bf16.h>
#include <stdint.h>
#include <math.h>

#define BN 4
#define CN 64
#define HN 128
#define WN 128
#define SN (HN*WN)      // 16384
#define NP (BN*SN)      // 65536

// Scratch (device globals; no allocations allowed)
__device__ float g_y1[NP*CN];   // layer-1 output, NCHW
__device__ float g_rfh[NP];     // rf_h / 2
__device__ float g_rfw[NP];     // rf_w / 2

// ---------------- smem layout (dynamic) ----------------
// B tiles: [9 taps][64 o rows x 64 c cols] bf16, SW128-swizzled, 8KB/tap
#define B_HI_OFF 0
#define B_LO_OFF 73728
// A tile:  [128 px rows x 64 c cols] bf16, SW128-swizzled, 16KB
#define A_HI_OFF 147456
#define A_LO_OFF 163840
#define BIAS_OFF 180224
#define SMEM_TOTAL 180480

__device__ __forceinline__ uint32_t swz(uint32_t off) { return off ^ ((off >> 3) & 0x70); }
__device__ __forceinline__ uint32_t pk2(float a, float b) {
    __nv_bfloat162 t = __floats2bfloat162_rn(a, b);
    return *(uint32_t*)&t;
}

__device__ __forceinline__ void mma_bf16(float& d0, float& d1, float& d2, float& d3,
                                         uint32_t a0, uint32_t a1, uint32_t a2, uint32_t a3,
                                         uint32_t b0, uint32_t b1)
{
    asm volatile("mma.sync.aligned.m16n8k16.row.col.f32.bf16.bf16.f32 "
                 "{%0,%1,%2,%3}, {%4,%5,%6,%7}, {%8,%9}, {%0,%1,%2,%3};"
                 : "+f"(d0), "+f"(d1), "+f"(d2), "+f"(d3)
                 : "r"(a0), "r"(a1), "r"(a2), "r"(a3), "r"(b0), "r"(b1));
}

// ---------------------------------------------------------------------------
// Offset conv (NCHW) — unchanged (known good).
// ---------------------------------------------------------------------------
__global__ __launch_bounds__(256)
void offset_conv(const float* __restrict__ xin,
                 const float* __restrict__ woff,
                 const float* __restrict__ boff,
                 const int* __restrict__ p_lo, const int* __restrict__ p_hi,
                 float* __restrict__ rfh, float* __restrict__ rfw)
{
    __shared__ float sw[CN * 18];
    for (int d = threadIdx.x; d < CN * 18; d += 256) {
        int c = d / 18;
        int k = (d % 18) >> 1;
        int j = d & 1;
        sw[d] = woff[(j * CN + c) * 9 + k];
    }
    __syncthreads();

    int p  = blockIdx.x * 256 + threadIdx.x;
    int b  = p >> 14;
    int hw = p & (SN - 1);
    int h  = hw >> 7;
    int w  = hw & (WN - 1);

    bool hm = h > 0, hp = h < HN - 1, wm = w > 0, wp = w < WN - 1;

    float a0 = boff[0], a1 = boff[1];
    const float* xb = xin + (size_t)b * CN * SN;

    #pragma unroll 2
    for (int c = 0; c < CN; c++) {
        const float* xc = xb + c * SN + hw;
        float v[9];
        v[4] = xc[0];
        v[1] = hm ? xc[-WN] : 0.f;
        v[7] = hp ? xc[ WN] : 0.f;
        v[3] = wm ? xc[-1] : 0.f;
        v[5] = wp ? xc[ 1] : 0.f;
        v[0] = (hm && wm) ? xc[-WN - 1] : 0.f;
        v[2] = (hm && wp) ? xc[-WN + 1] : 0.f;
        v[6] = (hp && wm) ? xc[ WN - 1] : 0.f;
        v[8] = (hp && wp) ? xc[ WN + 1] : 0.f;
        const float* wc = sw + c * 18;
        #pragma unroll
        for (int k = 0; k < 9; k++) {
            a0 += v[k] * wc[k * 2 + 0];
            a1 += v[k] * wc[k * 2 + 1];
        }
    }

    float lo   = (float)(*p_lo);
    float span = (float)(*p_hi) - lo;
    float s0 = 1.f / (1.f + __expf(-a0));
    float s1 = 1.f / (1.f + __expf(-a1));
    rfh[p] = 0.5f * (lo + span * s0);
    rfw[p] = 0.5f * (lo + span * s1);
}

// ---------------------------------------------------------------------------
// mma.sync ARConv: per 128-pixel tile, GEMM [128px x 64o] = A[128x576] W[576x64]
// with K split as 9 taps x 4 chunks of 16 channels. bf16 hi/lo 3-term split
// => fp32-accurate. 4 tiles per CTA. 256 threads (8 warps, 16 px each).
// ---------------------------------------------------------------------------
__global__ __launch_bounds__(256, 1)
void arconv_mma(const float* __restrict__ xin,
                const float* __restrict__ rfh, const float* __restrict__ rfw,
                const float* __restrict__ Wk,      // [O][C][3][3]
                const float* __restrict__ bias,    // [O]
                const float* __restrict__ resid,   // NCHW (mode 1) or null
                float* __restrict__ outp,
                int mode)
{
    extern __shared__ char smem[];
    int tid = threadIdx.x, wid = tid >> 5, lid = tid & 31;
    int g = lid >> 2, t = lid & 3;   // mma quad coords

    // B hi/lo conversion into SW128-swizzled tap tiles [o rows x c cols]
    for (int d = tid; d < 9 * 64 * 64; d += 256) {
        int tap = d >> 12;
        int o   = (d >> 6) & 63;
        int c   = d & 63;
        float wv = Wk[(o * 64 + c) * 9 + tap];
        __nv_bfloat16 hb = __float2bfloat16(wv);
        float hf = __bfloat162float(hb);
        __nv_bfloat16 lb = __float2bfloat16(wv - hf);
        uint32_t s = tap * 8192 + swz((uint32_t)(o * 128 + c * 2));
        *(__nv_bfloat16*)(smem + B_HI_OFF + s) = hb;
        *(__nv_bfloat16*)(smem + B_LO_OFF + s) = lb;
    }
    if (tid < 64) *(float*)(smem + BIAS_OFF + tid * 4) = bias[tid];
    __syncthreads();

    const float* biasS = (const float*)(smem + BIAS_OFF);

    for (int it = 0; it < 4; it++) {
        int tile = blockIdx.x * 4 + it;
        int p0 = tile * 128;

        // ---- per-pixel sampling geometry (producer role) ----
        int px = tid & 127;
        int cbase = (tid >> 7) * 32;
        int p = p0 + px;
        int b = p >> 14;
        int hw = p & (SN - 1);
        int h = hw >> 7;
        int w = hw & (WN - 1);

        float rh = rfh[p];
        float rw = rfw[p];

        float xsl = (float)w - rw, xsr = (float)w + rw;
        float xl0f = floorf(xsl), xr0f = floorf(xsr);
        float txl = xsl - xl0f, txr = xsr - xr0f;
        int xl0 = min(max((int)xl0f, 0), WN - 1); int xl1 = min(xl0 + 1, WN - 1);
        int xr0 = min(max((int)xr0f, 0), WN - 1); int xr1 = min(xr0 + 1, WN - 1);

        float ysa = (float)h - rh, ysb = (float)h + rh;
        float ya0f = floorf(ysa), yb0f = floorf(ysb);
        float tya = ysa - ya0f, tyb = ysb - yb0f;
        int ya0 = min(max((int)ya0f, 0), HN - 1); int ya1 = min(ya0 + 1, HN - 1);
        int yb0 = min(max((int)yb0f, 0), HN - 1); int yb1 = min(yb0 + 1, HN - 1);

        int oa0 = ya0 * WN, oa1 = ya1 * WN, ohh = h * WN, ob0 = yb0 * WN, ob1 = yb1 * WN;

        const float* xb = xin + (size_t)(b * CN + cbase) * SN;

        // mma accumulators: [nb][c0..c3]
        float acc[8][4];
        #pragma unroll
        for (int nb = 0; nb < 8; nb++)
            #pragma unroll
            for (int j = 0; j < 4; j++) acc[nb][j] = 0.f;

        #pragma unroll 1
        for (int tap = 0; tap < 9; tap++) {
            int ky = (tap >= 6) ? 2 : (tap >= 3) ? 1 : 0;
            int kx = tap - ky * 3;

            int ry0 = (ky == 0) ? oa0 : (ky == 1) ? ohh : ob0;
            int ry1 = (ky == 0) ? oa1 : (ky == 1) ? ohh : ob1;
            float tyv = (ky == 0) ? tya : (ky == 1) ? 0.f : tyb;
            int x0 = (kx == 0) ? xl0 : (kx == 1) ? w : xr0;
            int x1 = (kx == 0) ? xl1 : (kx == 1) ? w : xr1;
            float txv = (kx == 0) ? txl : (kx == 1) ? 0.f : txr;
            bool cy = (ky == 1), cx = (kx == 1);

            // ---- produce A tile for this tap ----
            #pragma unroll 1
            for (int cg = 0; cg < 4; cg++) {
                const float* xc = xb + (size_t)(cg * 8) * SN;
                float v[8];
                if (cy && cx) {
                    #pragma unroll
                    for (int j = 0; j < 8; j++) v[j] = xc[(size_t)j * SN + ohh + w];
                } else if (cy) {
                    float q0[8], q1[8];
                    #pragma unroll
                    for (int j = 0; j < 8; j++) {
                        q0[j] = xc[(size_t)j * SN + ohh + x0];
                        q1[j] = xc[(size_t)j * SN + ohh + x1];
                    }
                    #pragma unroll
                    for (int j = 0; j < 8; j++) v[j] = fmaf(txv, q1[j] - q0[j], q0[j]);
                } else if (cx) {
                    float q0[8], q1[8];
                    #pragma unroll
                    for (int j = 0; j < 8; j++) {
                        q0[j] = xc[(size_t)j * SN + ry0 + w];
                        q1[j] = xc[(size_t)j * SN + ry1 + w];
                    }
                    #pragma unroll
                    for (int j = 0; j < 8; j++) v[j] = fmaf(tyv, q1[j] - q0[j], q0[j]);
                } else {
                    float a0[8], a1[8], c0[8], c1[8];
                    #pragma unroll
                    for (int j = 0; j < 8; j++) {
                        a0[j] = xc[(size_t)j * SN + ry0 + x0];
                        a1[j] = xc[(size_t)j * SN + ry0 + x1];
                        c0[j] = xc[(size_t)j * SN + ry1 + x0];
                        c1[j] = xc[(size_t)j * SN + ry1 + x1];
                    }
                    #pragma unroll
                    for (int j = 0; j < 8; j++) {
                        float t0 = fmaf(txv, a1[j] - a0[j], a0[j]);
                        float t1 = fmaf(txv, c1[j] - c0[j], c0[j]);
                        v[j] = fmaf(tyv, t1 - t0, t0);
                    }
                }

                float hf[8], lo[8];
                #pragma unroll
                for (int j = 0; j < 8; j++) {
                    __nv_bfloat16 hb = __float2bfloat16(v[j]);
                    hf[j] = __bfloat162float(hb);
                    lo[j] = v[j] - hf[j];
                }
                uint4 HV, LV;
                HV.x = pk2(hf[0], hf[1]); HV.y = pk2(hf[2], hf[3]);
                HV.z = pk2(hf[4], hf[5]); HV.w = pk2(hf[6], hf[7]);
                LV.x = pk2(lo[0], lo[1]); LV.y = pk2(lo[2], lo[3]);
                LV.z = pk2(lo[4], lo[5]); LV.w = pk2(lo[6], lo[7]);

                uint32_t s = swz((uint32_t)(px * 128 + (cbase + cg * 8) * 2));
                *(uint4*)(smem + A_HI_OFF + s) = HV;
                *(uint4*)(smem + A_LO_OFF + s) = LV;
            }

            __syncthreads();

            // ---- consume: warp wid computes px rows [16*wid, 16*wid+16) ----
            {
                int rbase = 16 * wid;
                uint32_t btap = tap * 8192;
                #pragma unroll
                for (int chunk = 0; chunk < 4; chunk++) {
                    int ck = chunk * 16;
                    uint32_t ar0 = swz((uint32_t)((rbase + g) * 128 + (ck + 2 * t) * 2));
                    uint32_t ar1 = swz((uint32_t)((rbase + g + 8) * 128 + (ck + 2 * t) * 2));
                    uint32_t ac0 = swz((uint32_t)((rbase + g) * 128 + (ck + 2 * t + 8) * 2));
                    uint32_t ac1 = swz((uint32_t)((rbase + g + 8) * 128 + (ck + 2 * t + 8) * 2));
                    uint32_t ah0 = *(const uint32_t*)(smem + A_HI_OFF + ar0);
                    uint32_t ah1 = *(const uint32_t*)(smem + A_HI_OFF + ar1);
                    uint32_t ah2 = *(const uint32_t*)(smem + A_HI_OFF + ac0);
                    uint32_t ah3 = *(const uint32_t*)(smem + A_HI_OFF + ac1);
                    uint32_t al0 = *(const uint32_t*)(smem + A_LO_OFF + ar0);
                    uint32_t al1 = *(const uint32_t*)(smem + A_LO_OFF + ar1);
                    uint32_t al2 = *(const uint32_t*)(smem + A_LO_OFF + ac0);
                    uint32_t al3 = *(const uint32_t*)(smem + A_LO_OFF + ac1);

                    #pragma unroll
                    for (int nb = 0; nb < 8; nb++) {
                        int o = nb * 8 + g;
                        uint32_t br0 = swz((uint32_t)(o * 128 + (ck + 2 * t) * 2));
                        uint32_t br1 = swz((uint32_t)(o * 128 + (ck + 2 * t + 8) * 2));
                        uint32_t bh0 = *(const uint32_t*)(smem + B_HI_OFF + btap + br0);
                        uint32_t bh1 = *(const uint32_t*)(smem + B_HI_OFF + btap + br1);
                        uint32_t bl0 = *(const uint32_t*)(smem + B_LO_OFF + btap + br0);
                        uint32_t bl1 = *(const uint32_t*)(smem + B_LO_OFF + btap + br1);

                        mma_bf16(acc[nb][0], acc[nb][1], acc[nb][2], acc[nb][3],
                                 ah0, ah1, ah2, ah3, bh0, bh1);
                        mma_bf16(acc[nb][0], acc[nb][1], acc[nb][2], acc[nb][3],
                                 al0, al1, al2, al3, bh0, bh1);
                        mma_bf16(acc[nb][0], acc[nb][1], acc[nb][2], acc[nb][3],
                                 ah0, ah1, ah2, ah3, bl0, bl1);
                    }
                }
            }
            __syncthreads();   // protect A before next tap's produce
        }

        // ---- epilogue: D fragment -> NCHW ----
        {
            int px0 = p0 + 16 * wid + g;      // rows g and g+8 of this warp's stripe
            int px1 = px0 + 8;
            int b0i = px0 >> 14, hw0 = px0 & (SN - 1);
            int b1i = px1 >> 14, hw1 = px1 & (SN - 1);
            #pragma unroll
            for (int nb = 0; nb < 8; nb++) {
                int o0 = nb * 8 + 2 * t;
                int o1 = o0 + 1;
                size_t i00 = ((size_t)(b0i * CN + o0)) * SN + hw0;
                size_t i01 = ((size_t)(b0i * CN + o1)) * SN + hw0;
                size_t i10 = ((size_t)(b1i * CN + o0)) * SN + hw1;
                size_t i11 = ((size_t)(b1i * CN + o1)) * SN + hw1;
                float v00 = acc[nb][0] + biasS[o0];
                float v01 = acc[nb][1] + biasS[o1];
                float v10 = acc[nb][2] + biasS[o0];
                float v11 = acc[nb][3] + biasS[o1];
                if (mode == 0) {
                    outp[i00] = fmaxf(v00, 0.f);
                    outp[i01] = fmaxf(v01, 0.f);
                    outp[i10] = fmaxf(v10, 0.f);
                    outp[i11] = fmaxf(v11, 0.f);
                } else {
                    outp[i00] = v00 + resid[i00];
                    outp[i01] = v01 + resid[i01];
                    outp[i10] = v10 + resid[i10];
                    outp[i11] = v11 + resid[i11];
                }
            }
        }
        __syncthreads();
    }
}

// ---------------------------------------------------------------------------
extern "C" void kernel_launch(void* const* d_in, const int* in_sizes, int n_in,
                              void* d_out, int out_size)
{
    const float* x     = (const float*)d_in[0];
    const float* woff1 = (const float*)d_in[1];
    const float* boff1 = (const float*)d_in[2];
    const float* W1    = (const float*)d_in[3];
    const float* b1    = (const float*)d_in[4];
    const float* woff2 = (const float*)d_in[5];
    const float* boff2 = (const float*)d_in[6];
    const float* W2    = (const float*)d_in[7];
    const float* b2    = (const float*)d_in[8];
    const int*   lo    = (const int*)d_in[10];
    const int*   hi    = (const int*)d_in[11];
    float* out = (float*)d_out;

    float *y1, *rfh, *rfw;
    cudaGetSymbolAddress((void**)&y1,  g_y1);
    cudaGetSymbolAddress((void**)&rfh, g_rfh);
    cudaGetSymbolAddress((void**)&rfw, g_rfw);

    cudaFuncSetAttribute(arconv_mma, cudaFuncAttributeMaxDynamicSharedMemorySize, SMEM_TOTAL);

    // Layer 1
    offset_conv<<<NP / 256, 256>>>(x, woff1, boff1, lo, hi, rfh, rfw);
    arconv_mma<<<128, 256, SMEM_TOTAL>>>(x, rfh, rfw, W1, b1, nullptr, y1, 0);

    // Layer 2 (+ residual)
    offset_conv<<<NP / 256, 256>>>(y1, woff2, boff2, lo, hi, rfh, rfw);
    arconv_mma<<<128, 256, SMEM_TOTAL>>>(y1, rfh, rfw, W2, b2, x, out, 1);
}